// round 1
// baseline (speedup 1.0000x reference)
#include <cuda_runtime.h>
#include <cuda_bf16.h>
#include <cstdint>

#define NMAX 100000
#define EMAX 1600000
#define D 128

// ---------------- static device scratch (no allocations allowed) ------------
__device__ int   g_deg[NMAX];
__device__ int   g_cursor[NMAX];
__device__ int   g_off[NMAX + 1];
__device__ int   g_csr[EMAX];
__device__ int   g_bsum[128];
__device__ int   g_bpre[128];
__device__ float g_mean[(size_t)NMAX * D];
__device__ float g_h0[(size_t)NMAX * D];
__device__ float g_h1[(size_t)NMAX * D];
// packed bf16 hi/lo weight fragments: [6 mats][128 n][8 ks][4 tig] as uint4
__device__ uint4 g_wfrag[6 * 128 * 8 * 4];

// ---------------- CSR build -------------------------------------------------
__global__ void k_zero(int n) {
    int i = blockIdx.x * blockDim.x + threadIdx.x;
    if (i < n) { g_deg[i] = 0; g_cursor[i] = 0; }
}

__global__ void k_deg(const int* __restrict__ ei, int E) {
    int e = blockIdx.x * blockDim.x + threadIdx.x;
    if (e < E) atomicAdd(&g_deg[ei[E + e]], 1);
}

__global__ void k_bsum(int n) {
    __shared__ int s[1024];
    int i = blockIdx.x * 1024 + threadIdx.x;
    s[threadIdx.x] = (i < n) ? g_deg[i] : 0;
    __syncthreads();
    for (int d = 512; d > 0; d >>= 1) {
        if (threadIdx.x < d) s[threadIdx.x] += s[threadIdx.x + d];
        __syncthreads();
    }
    if (threadIdx.x == 0) g_bsum[blockIdx.x] = s[0];
}

__global__ void k_scanbs(int nb) {
    if (threadIdx.x == 0) {
        int a = 0;
        for (int i = 0; i < nb; i++) { g_bpre[i] = a; a += g_bsum[i]; }
    }
}

__global__ void k_off(int n) {
    __shared__ int s[1024];
    int tid = threadIdx.x;
    int i = blockIdx.x * 1024 + tid;
    int v = (i < n) ? g_deg[i] : 0;
    s[tid] = v;
    __syncthreads();
    for (int d = 1; d < 1024; d <<= 1) {
        int t = (tid >= d) ? s[tid - d] : 0;
        __syncthreads();
        s[tid] += t;
        __syncthreads();
    }
    int excl = s[tid] - v + g_bpre[blockIdx.x];
    if (i < n) g_off[i] = excl;
    if (i == n - 1) g_off[n] = excl + v;
}

__global__ void k_fill(const int* __restrict__ ei, int E) {
    int e = blockIdx.x * blockDim.x + threadIdx.x;
    if (e >= E) return;
    int s = ei[e];
    int d = ei[E + e];
    int pos = atomicAdd(&g_cursor[d], 1);
    g_csr[g_off[d] + pos] = s;
}

// ---------------- weight pre-split into mma B-fragment order ----------------
__device__ __forceinline__ void split_pack2(float a, float b, uint32_t& hi, uint32_t& lo) {
    __nv_bfloat16 ha = __float2bfloat16(a);
    __nv_bfloat16 hb = __float2bfloat16(b);
    float ra = a - __bfloat162float(ha);
    float rb = b - __bfloat162float(hb);
    __nv_bfloat162 H = __halves2bfloat162(ha, hb);
    __nv_bfloat162 L = __halves2bfloat162(__float2bfloat16(ra), __float2bfloat16(rb));
    hi = *reinterpret_cast<uint32_t*>(&H);
    lo = *reinterpret_cast<uint32_t*>(&L);
}

// t = lm*4096 + n*32 + ks*4 + tig; source W is [K=128][N=128] row-major
__global__ void k_wprep(const float* __restrict__ Wl0, const float* __restrict__ Wr0,
                        const float* __restrict__ Wl, const float* __restrict__ Wr) {
    int t = blockIdx.x * blockDim.x + threadIdx.x;
    if (t >= 6 * 128 * 32) return;
    int tig = t & 3;
    int ks = (t >> 2) & 7;
    int n = (t >> 5) & 127;
    int lm = t >> 12;
    int layer = lm >> 1, mat = lm & 1;
    const float* W;
    if (layer == 0) W = mat ? Wr0 : Wl0;
    else W = (mat ? Wr : Wl) + (size_t)(layer - 1) * D * D;
    int k0 = ks * 16 + tig * 2;
    float w00 = W[(k0 + 0) * D + n];
    float w01 = W[(k0 + 1) * D + n];
    float w80 = W[(k0 + 8) * D + n];
    float w81 = W[(k0 + 9) * D + n];
    uint4 o;
    split_pack2(w00, w01, o.x, o.z);
    split_pack2(w80, w81, o.y, o.w);
    g_wfrag[t] = o;
}

// ---------------- mean aggregation: 1 warp per node -------------------------
__global__ void k_agg(const float* __restrict__ h, int N) {
    int warp = (blockIdx.x * blockDim.x + threadIdx.x) >> 5;
    int lane = threadIdx.x & 31;
    if (warp >= N) return;
    int beg = g_off[warp];
    int end = g_off[warp + 1];
    const float4* hv = (const float4*)h;
    float4 acc = make_float4(0.f, 0.f, 0.f, 0.f);
    int e = beg;
    for (; e + 4 <= end; e += 4) {
        int s0 = g_csr[e + 0], s1 = g_csr[e + 1], s2 = g_csr[e + 2], s3 = g_csr[e + 3];
        float4 v0 = hv[(size_t)s0 * 32 + lane];
        float4 v1 = hv[(size_t)s1 * 32 + lane];
        float4 v2 = hv[(size_t)s2 * 32 + lane];
        float4 v3 = hv[(size_t)s3 * 32 + lane];
        acc.x += (v0.x + v1.x) + (v2.x + v3.x);
        acc.y += (v0.y + v1.y) + (v2.y + v3.y);
        acc.z += (v0.z + v1.z) + (v2.z + v3.z);
        acc.w += (v0.w + v1.w) + (v2.w + v3.w);
    }
    for (; e < end; ++e) {
        int s = g_csr[e];
        float4 v = hv[(size_t)s * 32 + lane];
        acc.x += v.x; acc.y += v.y; acc.z += v.z; acc.w += v.w;
    }
    float scale = (end > beg) ? 1.f / (float)(end - beg) : 0.f;
    acc.x *= scale; acc.y *= scale; acc.z *= scale; acc.w *= scale;
    ((float4*)g_mean)[(size_t)warp * 32 + lane] = acc;
}

// ---------------- fused GEMM (bf16x3 split) + bias + LayerNorm + ReLU -------
__device__ __forceinline__ void mma16816(float c[4], const uint32_t a[4],
                                         uint32_t b0, uint32_t b1) {
    asm volatile(
        "mma.sync.aligned.m16n8k16.row.col.f32.bf16.bf16.f32 "
        "{%0,%1,%2,%3}, {%4,%5,%6,%7}, {%8,%9}, {%0,%1,%2,%3};\n"
        : "+f"(c[0]), "+f"(c[1]), "+f"(c[2]), "+f"(c[3])
        : "r"(a[0]), "r"(a[1]), "r"(a[2]), "r"(a[3]), "r"(b0), "r"(b1));
}

__global__ void __launch_bounds__(256)
k_gemm_ln(const float* __restrict__ h, int layer,
          const float* __restrict__ bias, const float* __restrict__ gamma,
          const float* __restrict__ beta, float* __restrict__ out, int N) {
    const uint4* wL = g_wfrag + (size_t)(layer * 2 + 0) * 4096;
    const uint4* wR = g_wfrag + (size_t)(layer * 2 + 1) * 4096;
    const float* mean = g_mean;

    int warp = threadIdx.x >> 5;
    int lane = threadIdx.x & 31;
    int g = lane >> 2;
    int tig = lane & 3;
    int rowbase = blockIdx.x * 128 + warp * 16;
    int rA = rowbase + g;
    int rB = rowbase + g + 8;
    int rAc = min(rA, N - 1);
    int rBc = min(rB, N - 1);
    const float* mA = mean + (size_t)rAc * D;
    const float* mB = mean + (size_t)rBc * D;
    const float* hA = h + (size_t)rAc * D;
    const float* hB = h + (size_t)rBc * D;

    float acc[16][4];
#pragma unroll
    for (int i = 0; i < 16; i++) {
        acc[i][0] = 0.f; acc[i][1] = 0.f; acc[i][2] = 0.f; acc[i][3] = 0.f;
    }

#pragma unroll 1
    for (int ks = 0; ks < 8; ++ks) {
        int k0 = ks * 16 + tig * 2;
        float2 ma0 = *(const float2*)(mA + k0);
        float2 ma1 = *(const float2*)(mB + k0);
        float2 ma2 = *(const float2*)(mA + k0 + 8);
        float2 ma3 = *(const float2*)(mB + k0 + 8);
        float2 ha0 = *(const float2*)(hA + k0);
        float2 ha1 = *(const float2*)(hB + k0);
        float2 ha2 = *(const float2*)(hA + k0 + 8);
        float2 ha3 = *(const float2*)(hB + k0 + 8);

        uint32_t Mhi[4], Mlo[4], Hhi[4], Hlo[4];
        split_pack2(ma0.x, ma0.y, Mhi[0], Mlo[0]);
        split_pack2(ma1.x, ma1.y, Mhi[1], Mlo[1]);
        split_pack2(ma2.x, ma2.y, Mhi[2], Mlo[2]);
        split_pack2(ma3.x, ma3.y, Mhi[3], Mlo[3]);
        split_pack2(ha0.x, ha0.y, Hhi[0], Hlo[0]);
        split_pack2(ha1.x, ha1.y, Hhi[1], Hlo[1]);
        split_pack2(ha2.x, ha2.y, Hhi[2], Hlo[2]);
        split_pack2(ha3.x, ha3.y, Hhi[3], Hlo[3]);

        const uint4* pL = wL + ks * 4 + tig;
        const uint4* pR = wR + ks * 4 + tig;
#pragma unroll
        for (int nt = 0; nt < 16; ++nt) {
            int ncol = nt * 8 + g;
            uint4 fl = pL[ncol * 32];
            mma16816(acc[nt], Mhi, fl.x, fl.y);   // hi * hi
            mma16816(acc[nt], Mlo, fl.x, fl.y);   // lo * hi
            mma16816(acc[nt], Mhi, fl.z, fl.w);   // hi * lo
            uint4 fr = pR[ncol * 32];
            mma16816(acc[nt], Hhi, fr.x, fr.y);
            mma16816(acc[nt], Hlo, fr.x, fr.y);
            mma16816(acc[nt], Hhi, fr.z, fr.w);
        }
    }

    // epilogue: + bias, LayerNorm over the 128-wide row (4 lanes per row), ReLU
    float sA = 0.f, qA = 0.f, sB = 0.f, qB = 0.f;
#pragma unroll
    for (int nt = 0; nt < 16; ++nt) {
        int col = nt * 8 + tig * 2;
        float2 bv = *(const float2*)(bias + col);
        acc[nt][0] += bv.x; acc[nt][1] += bv.y;
        acc[nt][2] += bv.x; acc[nt][3] += bv.y;
        sA += acc[nt][0] + acc[nt][1];
        qA += acc[nt][0] * acc[nt][0] + acc[nt][1] * acc[nt][1];
        sB += acc[nt][2] + acc[nt][3];
        qB += acc[nt][2] * acc[nt][2] + acc[nt][3] * acc[nt][3];
    }
#pragma unroll
    for (int m = 1; m <= 2; m <<= 1) {
        sA += __shfl_xor_sync(0xffffffff, sA, m);
        qA += __shfl_xor_sync(0xffffffff, qA, m);
        sB += __shfl_xor_sync(0xffffffff, sB, m);
        qB += __shfl_xor_sync(0xffffffff, qB, m);
    }
    const float inv = 1.f / 128.f;
    float muA = sA * inv;
    float vA = fmaxf(qA * inv - muA * muA, 0.f);
    float rsA = rsqrtf(vA + 1e-5f);
    float muB = sB * inv;
    float vB = fmaxf(qB * inv - muB * muB, 0.f);
    float rsB = rsqrtf(vB + 1e-5f);

#pragma unroll
    for (int nt = 0; nt < 16; ++nt) {
        int col = nt * 8 + tig * 2;
        float2 gv = *(const float2*)(gamma + col);
        float2 bv = *(const float2*)(beta + col);
        if (rA < N) {
            float2 o;
            o.x = fmaxf(0.f, (acc[nt][0] - muA) * rsA * gv.x + bv.x);
            o.y = fmaxf(0.f, (acc[nt][1] - muA) * rsA * gv.y + bv.y);
            *(float2*)(out + (size_t)rA * D + col) = o;
        }
        if (rB < N) {
            float2 o;
            o.x = fmaxf(0.f, (acc[nt][2] - muB) * rsB * gv.x + bv.x);
            o.y = fmaxf(0.f, (acc[nt][3] - muB) * rsB * gv.y + bv.y);
            *(float2*)(out + (size_t)rB * D + col) = o;
        }
    }
}

// ---------------- launch ----------------------------------------------------
extern "C" void kernel_launch(void* const* d_in, const int* in_sizes, int n_in,
                              void* d_out, int out_size) {
    const float* x   = (const float*)d_in[0];
    const int*   ei  = (const int*)d_in[1];
    const float* Wl0 = (const float*)d_in[2];
    const float* bl0 = (const float*)d_in[3];
    const float* Wr0 = (const float*)d_in[4];
    const float* g0  = (const float*)d_in[5];
    const float* be0 = (const float*)d_in[6];
    const float* Wl  = (const float*)d_in[7];
    const float* bl  = (const float*)d_in[8];
    const float* Wr  = (const float*)d_in[9];
    const float* gg  = (const float*)d_in[10];
    const float* be  = (const float*)d_in[11];
    float* out = (float*)d_out;

    int N = in_sizes[0] / D;
    int E = in_sizes[1] / 2;

    float* h0;  cudaGetSymbolAddress((void**)&h0, g_h0);
    float* h1;  cudaGetSymbolAddress((void**)&h1, g_h1);

    int nb = (N + 1023) / 1024;

    // CSR build (once per launch; reused by all 3 layers)
    k_zero<<<(N + 255) / 256, 256>>>(N);
    k_deg<<<(E + 255) / 256, 256>>>(ei, E);
    k_bsum<<<nb, 1024>>>(N);
    k_scanbs<<<1, 32>>>(nb);
    k_off<<<nb, 1024>>>(N);
    k_fill<<<(E + 255) / 256, 256>>>(ei, E);

    // weight split + fragment swizzle
    k_wprep<<<(6 * 128 * 32 + 255) / 256, 256>>>(Wl0, Wr0, Wl, Wr);

    int agg_blocks = (N + 7) / 8;       // 1 warp per node, 8 warps per block
    int gemm_blocks = (N + 127) / 128;  // 128 rows per block

    // layer 0: x -> h0
    k_agg<<<agg_blocks, 256>>>(x, N);
    k_gemm_ln<<<gemm_blocks, 256>>>(x, 0, bl0, g0, be0, h0, N);
    // layer 1: h0 -> h1
    k_agg<<<agg_blocks, 256>>>(h0, N);
    k_gemm_ln<<<gemm_blocks, 256>>>(h0, 1, bl, gg, be, h1, N);
    // layer 2: h1 -> out
    k_agg<<<agg_blocks, 256>>>(h1, N);
    k_gemm_ln<<<gemm_blocks, 256>>>(h1, 2, bl + D, gg + D, be + D, out, N);
}

// round 2
// speedup vs baseline: 1.0131x; 1.0131x over previous
#include <cuda_runtime.h>
#include <cuda_bf16.h>
#include <cstdint>

#define NMAX 100000
#define EMAX 1600000
#define D 128

// ---------------- static device scratch (no allocations allowed) ------------
__device__ int   g_deg[NMAX];
__device__ int   g_cursor[NMAX];
__device__ int   g_off[NMAX + 1];
__device__ int   g_csr[EMAX];
__device__ int   g_bsum[128];
__device__ int   g_bpre[128];
__device__ float g_mean[(size_t)NMAX * D];
__device__ float g_h0[(size_t)NMAX * D];
__device__ float g_h1[(size_t)NMAX * D];
// packed bf16 hi/lo weight fragments: [6 mats][128 n][8 ks][4 tig] as uint4
__device__ uint4 g_wfrag[6 * 128 * 8 * 4];

// ---------------- CSR build -------------------------------------------------
__global__ void k_zero(int n) {
    int i = blockIdx.x * blockDim.x + threadIdx.x;
    if (i < n) { g_deg[i] = 0; g_cursor[i] = 0; }
}

__global__ void k_deg(const int* __restrict__ ei, int E) {
    int e = blockIdx.x * blockDim.x + threadIdx.x;
    if (e < E) atomicAdd(&g_deg[ei[E + e]], 1);
}

__global__ void k_bsum(int n) {
    __shared__ int s[1024];
    int i = blockIdx.x * 1024 + threadIdx.x;
    s[threadIdx.x] = (i < n) ? g_deg[i] : 0;
    __syncthreads();
    for (int d = 512; d > 0; d >>= 1) {
        if (threadIdx.x < d) s[threadIdx.x] += s[threadIdx.x + d];
        __syncthreads();
    }
    if (threadIdx.x == 0) g_bsum[blockIdx.x] = s[0];
}

__global__ void k_scanbs(int nb) {
    if (threadIdx.x == 0) {
        int a = 0;
        for (int i = 0; i < nb; i++) { g_bpre[i] = a; a += g_bsum[i]; }
    }
}

__global__ void k_off(int n) {
    __shared__ int s[1024];
    int tid = threadIdx.x;
    int i = blockIdx.x * 1024 + tid;
    int v = (i < n) ? g_deg[i] : 0;
    s[tid] = v;
    __syncthreads();
    for (int d = 1; d < 1024; d <<= 1) {
        int t = (tid >= d) ? s[tid - d] : 0;
        __syncthreads();
        s[tid] += t;
        __syncthreads();
    }
    int excl = s[tid] - v + g_bpre[blockIdx.x];
    if (i < n) g_off[i] = excl;
    if (i == n - 1) g_off[n] = excl + v;
}

__global__ void k_fill(const int* __restrict__ ei, int E) {
    int e = blockIdx.x * blockDim.x + threadIdx.x;
    if (e >= E) return;
    int s = ei[e];
    int d = ei[E + e];
    int pos = atomicAdd(&g_cursor[d], 1);
    g_csr[g_off[d] + pos] = s;
}

// ---------------- weight pre-split into mma B-fragment order ----------------
__device__ __forceinline__ void split_pack2(float a, float b, uint32_t& hi, uint32_t& lo) {
    __nv_bfloat16 ha = __float2bfloat16(a);
    __nv_bfloat16 hb = __float2bfloat16(b);
    float ra = a - __bfloat162float(ha);
    float rb = b - __bfloat162float(hb);
    __nv_bfloat162 H = __halves2bfloat162(ha, hb);
    __nv_bfloat162 L = __halves2bfloat162(__float2bfloat16(ra), __float2bfloat16(rb));
    hi = *reinterpret_cast<uint32_t*>(&H);
    lo = *reinterpret_cast<uint32_t*>(&L);
}

// t = lm*4096 + n*32 + ks*4 + tig; source W is [K=128][N=128] row-major
__global__ void k_wprep(const float* __restrict__ Wl0, const float* __restrict__ Wr0,
                        const float* __restrict__ Wl, const float* __restrict__ Wr) {
    int t = blockIdx.x * blockDim.x + threadIdx.x;
    if (t >= 6 * 128 * 32) return;
    int tig = t & 3;
    int ks = (t >> 2) & 7;
    int n = (t >> 5) & 127;
    int lm = t >> 12;
    int layer = lm >> 1, mat = lm & 1;
    const float* W;
    if (layer == 0) W = mat ? Wr0 : Wl0;
    else W = (mat ? Wr : Wl) + (size_t)(layer - 1) * D * D;
    int k0 = ks * 16 + tig * 2;
    float w00 = W[(k0 + 0) * D + n];
    float w01 = W[(k0 + 1) * D + n];
    float w80 = W[(k0 + 8) * D + n];
    float w81 = W[(k0 + 9) * D + n];
    uint4 o;
    split_pack2(w00, w01, o.x, o.z);
    split_pack2(w80, w81, o.y, o.w);
    g_wfrag[t] = o;
}

// ---------------- mean aggregation: 1 warp per node -------------------------
__global__ void k_agg(const float* __restrict__ h, int N) {
    int warp = (blockIdx.x * blockDim.x + threadIdx.x) >> 5;
    int lane = threadIdx.x & 31;
    if (warp >= N) return;
    int beg = g_off[warp];
    int end = g_off[warp + 1];
    const float4* hv = (const float4*)h;
    float4 acc = make_float4(0.f, 0.f, 0.f, 0.f);
    int e = beg;
    for (; e + 4 <= end; e += 4) {
        int s0 = g_csr[e + 0], s1 = g_csr[e + 1], s2 = g_csr[e + 2], s3 = g_csr[e + 3];
        float4 v0 = hv[(size_t)s0 * 32 + lane];
        float4 v1 = hv[(size_t)s1 * 32 + lane];
        float4 v2 = hv[(size_t)s2 * 32 + lane];
        float4 v3 = hv[(size_t)s3 * 32 + lane];
        acc.x += (v0.x + v1.x) + (v2.x + v3.x);
        acc.y += (v0.y + v1.y) + (v2.y + v3.y);
        acc.z += (v0.z + v1.z) + (v2.z + v3.z);
        acc.w += (v0.w + v1.w) + (v2.w + v3.w);
    }
    for (; e < end; ++e) {
        int s = g_csr[e];
        float4 v = hv[(size_t)s * 32 + lane];
        acc.x += v.x; acc.y += v.y; acc.z += v.z; acc.w += v.w;
    }
    float scale = (end > beg) ? 1.f / (float)(end - beg) : 0.f;
    acc.x *= scale; acc.y *= scale; acc.z *= scale; acc.w *= scale;
    ((float4*)g_mean)[(size_t)warp * 32 + lane] = acc;
}

// ---------------- fused GEMM (bf16x3 split) + bias + LayerNorm + ReLU -------
__device__ __forceinline__ void mma16816(float c[4], const uint32_t a[4],
                                         uint32_t b0, uint32_t b1) {
    asm volatile(
        "mma.sync.aligned.m16n8k16.row.col.f32.bf16.bf16.f32 "
        "{%0,%1,%2,%3}, {%4,%5,%6,%7}, {%8,%9}, {%0,%1,%2,%3};\n"
        : "+f"(c[0]), "+f"(c[1]), "+f"(c[2]), "+f"(c[3])
        : "r"(a[0]), "r"(a[1]), "r"(a[2]), "r"(a[3]), "r"(b0), "r"(b1));
}

__global__ void __launch_bounds__(256)
k_gemm_ln(const float* __restrict__ h, int layer,
          const float* __restrict__ bias, const float* __restrict__ gamma,
          const float* __restrict__ beta, float* __restrict__ out, int N) {
    const uint4* wL = g_wfrag + (size_t)(layer * 2 + 0) * 4096;
    const uint4* wR = g_wfrag + (size_t)(layer * 2 + 1) * 4096;
    const float* mean = g_mean;

    int warp = threadIdx.x >> 5;
    int lane = threadIdx.x & 31;
    int g = lane >> 2;
    int tig = lane & 3;
    int rowbase = blockIdx.x * 128 + warp * 16;
    int rA = rowbase + g;
    int rB = rowbase + g + 8;
    int rAc = min(rA, N - 1);
    int rBc = min(rB, N - 1);
    const float* mA = mean + (size_t)rAc * D;
    const float* mB = mean + (size_t)rBc * D;
    const float* hA = h + (size_t)rAc * D;
    const float* hB = h + (size_t)rBc * D;

    float acc[16][4];
#pragma unroll
    for (int i = 0; i < 16; i++) {
        acc[i][0] = 0.f; acc[i][1] = 0.f; acc[i][2] = 0.f; acc[i][3] = 0.f;
    }

#pragma unroll 1
    for (int ks = 0; ks < 8; ++ks) {
        int k0 = ks * 16 + tig * 2;
        float2 ma0 = *(const float2*)(mA + k0);
        float2 ma1 = *(const float2*)(mB + k0);
        float2 ma2 = *(const float2*)(mA + k0 + 8);
        float2 ma3 = *(const float2*)(mB + k0 + 8);
        float2 ha0 = *(const float2*)(hA + k0);
        float2 ha1 = *(const float2*)(hB + k0);
        float2 ha2 = *(const float2*)(hA + k0 + 8);
        float2 ha3 = *(const float2*)(hB + k0 + 8);

        uint32_t Mhi[4], Mlo[4], Hhi[4], Hlo[4];
        split_pack2(ma0.x, ma0.y, Mhi[0], Mlo[0]);
        split_pack2(ma1.x, ma1.y, Mhi[1], Mlo[1]);
        split_pack2(ma2.x, ma2.y, Mhi[2], Mlo[2]);
        split_pack2(ma3.x, ma3.y, Mhi[3], Mlo[3]);
        split_pack2(ha0.x, ha0.y, Hhi[0], Hlo[0]);
        split_pack2(ha1.x, ha1.y, Hhi[1], Hlo[1]);
        split_pack2(ha2.x, ha2.y, Hhi[2], Hlo[2]);
        split_pack2(ha3.x, ha3.y, Hhi[3], Hlo[3]);

        const uint4* pL = wL + ks * 4 + tig;
        const uint4* pR = wR + ks * 4 + tig;
#pragma unroll
        for (int nt = 0; nt < 16; ++nt) {
            int ncol = nt * 8 + g;
            uint4 fl = pL[ncol * 32];
            mma16816(acc[nt], Mhi, fl.x, fl.y);   // hi * hi
            mma16816(acc[nt], Mlo, fl.x, fl.y);   // lo * hi
            mma16816(acc[nt], Mhi, fl.z, fl.w);   // hi * lo
            uint4 fr = pR[ncol * 32];
            mma16816(acc[nt], Hhi, fr.x, fr.y);
            mma16816(acc[nt], Hlo, fr.x, fr.y);
            mma16816(acc[nt], Hhi, fr.z, fr.w);
        }
    }

    // epilogue: + bias, LayerNorm over the 128-wide row (4 lanes per row), ReLU
    float sA = 0.f, qA = 0.f, sB = 0.f, qB = 0.f;
#pragma unroll
    for (int nt = 0; nt < 16; ++nt) {
        int col = nt * 8 + tig * 2;
        float2 bv = *(const float2*)(bias + col);
        acc[nt][0] += bv.x; acc[nt][1] += bv.y;
        acc[nt][2] += bv.x; acc[nt][3] += bv.y;
        sA += acc[nt][0] + acc[nt][1];
        qA += acc[nt][0] * acc[nt][0] + acc[nt][1] * acc[nt][1];
        sB += acc[nt][2] + acc[nt][3];
        qB += acc[nt][2] * acc[nt][2] + acc[nt][3] * acc[nt][3];
    }
#pragma unroll
    for (int m = 1; m <= 2; m <<= 1) {
        sA += __shfl_xor_sync(0xffffffff, sA, m);
        qA += __shfl_xor_sync(0xffffffff, qA, m);
        sB += __shfl_xor_sync(0xffffffff, sB, m);
        qB += __shfl_xor_sync(0xffffffff, qB, m);
    }
    const float inv = 1.f / 128.f;
    float muA = sA * inv;
    float vA = fmaxf(qA * inv - muA * muA, 0.f);
    float rsA = rsqrtf(vA + 1e-5f);
    float muB = sB * inv;
    float vB = fmaxf(qB * inv - muB * muB, 0.f);
    float rsB = rsqrtf(vB + 1e-5f);

#pragma unroll
    for (int nt = 0; nt < 16; ++nt) {
        int col = nt * 8 + tig * 2;
        float2 gv = *(const float2*)(gamma + col);
        float2 bv = *(const float2*)(beta + col);
        if (rA < N) {
            float2 o;
            o.x = fmaxf(0.f, (acc[nt][0] - muA) * rsA * gv.x + bv.x);
            o.y = fmaxf(0.f, (acc[nt][1] - muA) * rsA * gv.y + bv.y);
            *(float2*)(out + (size_t)rA * D + col) = o;
        }
        if (rB < N) {
            float2 o;
            o.x = fmaxf(0.f, (acc[nt][2] - muB) * rsB * gv.x + bv.x);
            o.y = fmaxf(0.f, (acc[nt][3] - muB) * rsB * gv.y + bv.y);
            *(float2*)(out + (size_t)rB * D + col) = o;
        }
    }
}

// ---------------- launch ----------------------------------------------------
extern "C" void kernel_launch(void* const* d_in, const int* in_sizes, int n_in,
                              void* d_out, int out_size) {
    const float* x   = (const float*)d_in[0];
    const int*   ei  = (const int*)d_in[1];
    const float* Wl0 = (const float*)d_in[2];
    const float* bl0 = (const float*)d_in[3];
    const float* Wr0 = (const float*)d_in[4];
    const float* g0  = (const float*)d_in[5];
    const float* be0 = (const float*)d_in[6];
    const float* Wl  = (const float*)d_in[7];
    const float* bl  = (const float*)d_in[8];
    const float* Wr  = (const float*)d_in[9];
    const float* gg  = (const float*)d_in[10];
    const float* be  = (const float*)d_in[11];
    float* out = (float*)d_out;

    int N = in_sizes[0] / D;
    int E = in_sizes[1] / 2;

    float* h0;  cudaGetSymbolAddress((void**)&h0, g_h0);
    float* h1;  cudaGetSymbolAddress((void**)&h1, g_h1);

    int nb = (N + 1023) / 1024;

    // CSR build (once per launch; reused by all 3 layers)
    k_zero<<<(N + 255) / 256, 256>>>(N);
    k_deg<<<(E + 255) / 256, 256>>>(ei, E);
    k_bsum<<<nb, 1024>>>(N);
    k_scanbs<<<1, 32>>>(nb);
    k_off<<<nb, 1024>>>(N);
    k_fill<<<(E + 255) / 256, 256>>>(ei, E);

    // weight split + fragment swizzle
    k_wprep<<<(6 * 128 * 32 + 255) / 256, 256>>>(Wl0, Wr0, Wl, Wr);

    int agg_blocks = (N + 7) / 8;       // 1 warp per node, 8 warps per block
    int gemm_blocks = (N + 127) / 128;  // 128 rows per block

    // layer 0: x -> h0
    k_agg<<<agg_blocks, 256>>>(x, N);
    k_gemm_ln<<<gemm_blocks, 256>>>(x, 0, bl0, g0, be0, h0, N);
    // layer 1: h0 -> h1
    k_agg<<<agg_blocks, 256>>>(h0, N);
    k_gemm_ln<<<gemm_blocks, 256>>>(h0, 1, bl, gg, be, h1, N);
    // layer 2: h1 -> out
    k_agg<<<agg_blocks, 256>>>(h1, N);
    k_gemm_ln<<<gemm_blocks, 256>>>(h1, 2, bl + D, gg + D, be + D, out, N);
}